// round 10
// baseline (speedup 1.0000x reference)
#include <cuda_runtime.h>

#define N 4096
#define NN (N*N)
#define CIN 64
#define COUT 64
#define RWR 4
#define ITERS 10
#define BW 256          // bucket width (max supported row degree)
#define JB 16           // persistent blocks (co-resident trivially)
#define JT 256

// ---------------- device scratch (static globals: no allocations) ----------------
__device__ __align__(16) float g_L[NN];       // 64MB Jacobi working matrix
__device__ int   g_cursor[N];                 // per-row fill cursor == degree
__device__ int   g_bucket[N*BW];              // 4MB fixed-width adjacency
__device__ __align__(16) float g_dinv[N];
__device__ __align__(16) float g_aux[N*CIN];
__device__ float g_G1[CIN*COUT];              // [i][o]
__device__ int   g_is64;
__device__ int   g_rotk[ITERS], g_rotl[ITERS];
__device__ float g_rotc[ITERS], g_rots[ITERS];
__device__ float g_rowval[N];                 // per-row lexmax (or -2 sentinel = flagged)
__device__ int   g_rowidx[N];
__device__ int   g_rlist[ITERS*N];            // per-iteration flagged-row lists
__device__ int   g_rn[ITERS];
__device__ unsigned g_arrG;
__device__ unsigned g_barcnt;
__device__ volatile unsigned g_barsense;

__device__ __forceinline__ int edge_at(const int* e, int j) {
    return g_is64 ? e[2*j] : e[j];      // int64: value in low word
}

__device__ __forceinline__ void lexmax(float& bv, int& bi, float v, int i) {
    if (v > bv || (v == bv && i < bi)) { bv = v; bi = i; }
}

__device__ __forceinline__ void block_lexmax(float* sv, int* si, int tid, int nthr) {
    for (int off = nthr/2; off > 0; off >>= 1) {
        if (tid < off) {
            float v = sv[tid+off]; int c = si[tid+off];
            if (v > sv[tid] || (v == sv[tid] && c < si[tid])) { sv[tid] = v; si[tid] = c; }
        }
        __syncthreads();
    }
}

// sense-reversing grid barrier across JB blocks
__device__ __forceinline__ void gbar(unsigned& sense) {
    __syncthreads();
    sense ^= 1u;
    if (threadIdx.x == 0) {
        __threadfence();
        if (atomicAdd(&g_barcnt, 1u) == JB - 1u) {
            g_barcnt = 0u;
            __threadfence();
            g_barsense = sense;
        } else {
            while (g_barsense != sense) __nanosleep(20);
        }
    }
    __syncthreads();
}

// ---------------- setup ----------------
__global__ void k_setup(const int* e) {
    int t = blockIdx.x*blockDim.x + threadIdx.x;
    if (t < N) g_cursor[t] = 0;
    if (t < ITERS) g_rn[t] = 0;
    if (t == 0) {
        int nz = 0;
        for (int j = 1; j < 512; j += 2) nz |= (e[j] != 0);
        g_is64 = nz ? 0 : 1;
        g_arrG = 0u; g_barcnt = 0u; g_barsense = 0u;
    }
}

// scatter all E directed edges into fixed-width buckets; cursor becomes degree
__global__ void k_bucket(const int* e, int E) {
    for (int j = blockIdx.x*blockDim.x + threadIdx.x; j < E; j += gridDim.x*blockDim.x) {
        int r = edge_at(e, j);
        int c = edge_at(e, E + j);
        int p = atomicAdd(&g_cursor[r], 1);
        if (p < BW) g_bucket[r*BW + p] = c;
    }
}

__global__ void k_dinv() {
    int t = blockIdx.x*blockDim.x + threadIdx.x;
    if (t < N) {
        float d = (float)g_cursor[t];
        g_dinv[t] = (d > 0.0f) ? __fdiv_rn(1.0f, __fsqrt_rn(d)) : 0.0f;
    }
}

// Write L from scratch; fused per-row strict-upper lexmax.
__global__ void k_transform_rowmax() {
    __shared__ __align__(16) float cnt[N];
    __shared__ float sv[256];
    __shared__ int   si[256];
    int i = blockIdx.x, tid = threadIdx.x;
    for (int j = tid; j < N; j += 256) cnt[j] = 0.0f;
    __syncthreads();
    int deg = g_cursor[i];
    for (int p = tid; p < deg; p += 256) atomicAdd(&cnt[g_bucket[i*BW + p]], 1.0f);
    __syncthreads();
    float di = g_dinv[i];
    float4* row = (float4*)(g_L + (size_t)i*N);
    const float4* dv4 = (const float4*)g_dinv;
    float best = -1.0f; int bcol = 0x7FFFFFFF;
    for (int t4 = tid; t4 < N/4; t4 += 256) {
        int j = t4*4;
        float4 dj = dv4[t4];
        float4 cv = *((float4*)&cnt[j]);
        float4 o;
        o.x = __fsub_rn((i==j  )?1.0f:0.0f, __fmul_rn(__fmul_rn(di, cv.x), dj.x));
        o.y = __fsub_rn((i==j+1)?1.0f:0.0f, __fmul_rn(__fmul_rn(di, cv.y), dj.y));
        o.z = __fsub_rn((i==j+2)?1.0f:0.0f, __fmul_rn(__fmul_rn(di, cv.z), dj.z));
        o.w = __fsub_rn((i==j+3)?1.0f:0.0f, __fmul_rn(__fmul_rn(di, cv.w), dj.w));
        row[t4] = o;
        if (j+0 > i) lexmax(best, bcol, fabsf(o.x), j+0);
        if (j+1 > i) lexmax(best, bcol, fabsf(o.y), j+1);
        if (j+2 > i) lexmax(best, bcol, fabsf(o.z), j+2);
        if (j+3 > i) lexmax(best, bcol, fabsf(o.w), j+3);
    }
    sv[tid] = best; si[tid] = bcol;
    __syncthreads();
    block_lexmax(sv, si, tid, 256);
    if (tid == 0) { g_rowval[i] = sv[0]; g_rowidx[i] = si[0]; }
}

// ---------------- Cayley filter helper ----------------
__device__ __forceinline__ float g_entry(float wv, float hoi,
                                         const float* rw, const float* iw, float cval) {
    float hw = __fmul_rn(hoi, wv);
    float a2 = (hw > 1e-5f) ? 2.0f * atanf(__fdiv_rn(1.0f, hw)) : 2.0f;
    float acc = cval;
#pragma unroll
    for (int r = 0; r < RWR; r++) {
        float th = a2 * (float)(r + 1);
        float sn, cs;
        sincosf(th, &sn, &cs);
        acc += rw[r]*cs - iw[r]*sn;
    }
    return acc;
}

// ---------------- persistent Jacobi loop (2 barriers/iter) + tail ----------------
__global__ void __launch_bounds__(JT, 1) k_jacobi(const float* h, const float* rw,
        const float* iw, const float* cc, const float* x) {
    const int tid = threadIdx.x, bid = blockIdx.x;
    const int gt = bid*JT + tid;          // row owned by this thread (JB*JT == N)
    const int lane = tid & 31, wid = tid >> 5;
    unsigned sense = 0u;
    __shared__ float sv[JT];
    __shared__ int   si[JT];
    __shared__ float smv[N];              // rescan results, keyed by row
    __shared__ int   smi[N];
    __shared__ unsigned char sflag[N];
    __shared__ int sk, sl; __shared__ float scc, sss;

    for (int it = 0; it < ITERS; it++) {
        // ===== P1 (reads L only): rescan flagged rows + redundant argmax + params =====
        for (int j = tid; j < N; j += JT) sflag[j] = 0;
        __syncthreads();
        int nr = (it > 0) ? __ldcg(&g_rn[it-1]) : 0;
        for (int b = wid; b < nr; b += JT/32) {           // warp per flagged row
            int row = __ldcg(&g_rlist[(it-1)*N + b]);
            float best = -1.0f; int bcol = 0x7FFFFFFF;
            for (int j = row + 1 + lane; j < N; j += 32) {
                float a = fabsf(__ldcg(&g_L[(size_t)row*N + j]));
                if (a > best || (a == best && j < bcol)) { best = a; bcol = j; }
            }
#pragma unroll
            for (int off = 16; off > 0; off >>= 1) {
                float v = __shfl_down_sync(0xFFFFFFFFu, best, off);
                int   c = __shfl_down_sync(0xFFFFFFFFu, bcol, off);
                if (v > best || (v == best && c < bcol)) { best = v; bcol = c; }
            }
            if (lane == 0) { smv[row] = best; smi[row] = bcol; sflag[row] = 1; }
        }
        __syncthreads();
        // redundant global argmax (sentinel rows replaced by shared rescan values)
        float best = -1.0f; int bflat = 0x7FFFFFFF;
        for (int i = tid; i < N; i += JT) {
            float v; int col;
            if (sflag[i]) { v = smv[i]; col = smi[i]; }
            else {
                v = __ldcg(&g_rowval[i]);
                col = (v >= 0.0f) ? __ldcg(&g_rowidx[i]) : 0;
            }
            if (v >= 0.0f) {
                int flat = i*N + col;
                if (v > best || (v == best && flat < bflat)) { best = v; bflat = flat; }
            }
        }
        sv[tid] = best; si[tid] = bflat;
        __syncthreads();
        block_lexmax(sv, si, tid, JT);
        if (tid == 0) {
            int idx = si[0];
            int k = idx >> 12, l = idx & (N-1);
            float akl = __ldcg(&g_L[(size_t)k*N + l]);
            float akk = __ldcg(&g_L[(size_t)k*N + k]);
            float all = __ldcg(&g_L[(size_t)l*N + l]);
            float aDiff = __fsub_rn(all, akk);
            float akl_safe   = (akl   == 0.0f) ? 1.0f : akl;
            float aDiff_safe = (aDiff == 0.0f) ? 1.0f : aDiff;
            float phi = __fdiv_rn(aDiff, __fmul_rn(2.0f, akl_safe));
            float t2 = __fdiv_rn(1.0f, __fadd_rn(fabsf(phi),
                         __fsqrt_rn(__fadd_rn(__fmul_rn(phi, phi), 1.0f))));
            if (phi < 0.0f) t2 = -t2;
            float t1 = __fdiv_rn(akl, aDiff_safe);
            float tt = (fabsf(akl) < __fmul_rn(fabsf(aDiff), 1e-36f)) ? t1 : t2;
            float cv = __fdiv_rn(1.0f, __fsqrt_rn(__fadd_rn(__fmul_rn(tt, tt), 1.0f)));
            float ss2 = __fmul_rn(tt, cv);
            sk = k; sl = l; scc = cv; sss = ss2;
            g_rotk[it] = k; g_rotl[it] = l; g_rotc[it] = cv; g_rots[it] = ss2;  // identical dup writes
        }
        gbar(sense);   // all blocks done reading L / rowval before anyone writes

        // ===== P2 (writes): rotate + incremental rowmax + flag =====
        {
            int k = sk, l = sl;
            float c = scc, s = sss;
            int i = gt;
            if (i != k && i != l) {
                float ck = __ldcg(&g_L[(size_t)i*N + k]), cl = __ldcg(&g_L[(size_t)i*N + l]);
                float nk = __fsub_rn(__fmul_rn(c, ck), __fmul_rn(s, cl));
                float nl = __fadd_rn(__fmul_rn(s, ck), __fmul_rn(c, cl));
                g_L[(size_t)i*N + k] = nk;
                g_L[(size_t)i*N + l] = nl;
                float rk = __ldcg(&g_L[(size_t)k*N + i]), rl = __ldcg(&g_L[(size_t)l*N + i]);
                g_L[(size_t)k*N + i] = __fsub_rn(__fmul_rn(c, rk), __fmul_rn(s, rl));
                g_L[(size_t)l*N + i] = __fadd_rn(__fmul_rn(s, rk), __fmul_rn(c, rl));
                float bv; int bj;
                if (sflag[i]) { bv = smv[i]; bj = smi[i]; }
                else { bv = __ldcg(&g_rowval[i]); bj = __ldcg(&g_rowidx[i]); }
                if (bv >= 0.0f && (bj == k || bj == l)) {
                    int p = atomicAdd(&g_rn[it], 1);
                    g_rlist[it*N + p] = i;
                    g_rowval[i] = -2.0f;                  // sentinel: needs rescan
                } else {
                    if (k > i) { float a = fabsf(nk); if (a > bv || (a == bv && k < bj)) { bv = a; bj = k; } }
                    if (l > i) { float a = fabsf(nl); if (a > bv || (a == bv && l < bj)) { bv = a; bj = l; } }
                    g_rowval[i] = bv; g_rowidx[i] = bj;
                }
            } else if (i == k) {
                float akk = __ldcg(&g_L[(size_t)k*N + k]), akl = __ldcg(&g_L[(size_t)k*N + l]);
                float alk = __ldcg(&g_L[(size_t)l*N + k]), all = __ldcg(&g_L[(size_t)l*N + l]);
                float akk1 = __fsub_rn(__fmul_rn(c, akk), __fmul_rn(s, akl));
                float akl1 = __fadd_rn(__fmul_rn(s, akk), __fmul_rn(c, akl));
                float alk1 = __fsub_rn(__fmul_rn(c, alk), __fmul_rn(s, all));
                float all1 = __fadd_rn(__fmul_rn(s, alk), __fmul_rn(c, all));
                float akk2 = __fsub_rn(__fmul_rn(c, akk1), __fmul_rn(s, alk1));
                float all2 = __fadd_rn(__fmul_rn(s, akl1), __fmul_rn(c, all1));
                g_L[(size_t)k*N + k] = akk2;
                g_L[(size_t)l*N + l] = all2;
                g_L[(size_t)k*N + l] = 0.0f;
                g_L[(size_t)l*N + k] = 0.0f;
                int p = atomicAdd(&g_rn[it], 2);
                g_rlist[it*N + p] = k; g_rlist[it*N + p + 1] = l;
                g_rowval[k] = -2.0f; g_rowval[l] = -2.0f;
            }
        }
        gbar(sense);   // writes visible before next P1 reads
    }

    // ===== tail: aux = x (all blocks); G1 (block 1); auxrot (block 0) =====
    {
        const float4* xi = (const float4*)x;
        float4* ao = (float4*)g_aux;
        for (int i = gt; i < N*CIN/4; i += JB*JT) ao[i] = xi[i];
    }
    if (bid == 1) {
        for (int t = tid; t < COUT*CIN; t += JT) {
            int o = t >> 6, i2 = t & 63;
            int oi = o*CIN + i2;
            g_G1[i2*COUT + o] = g_entry(1.0f, h[oi], rw + oi*RWR, iw + oi*RWR, cc[oi]);
        }
    }
    gbar(sense);
    if (bid == 0 && tid < CIN) {   // aux = U^T x (apply R1^T first); column-independent
        int o = tid;
        for (int t = 0; t < ITERS; t++) {
            int k = g_rotk[t], l = g_rotl[t];
            float c = g_rotc[t], s = g_rots[t];
            float xk = __ldcg(&g_aux[k*CIN + o]), xl = __ldcg(&g_aux[l*CIN + o]);
            g_aux[k*CIN + o] = c*xk - s*xl;
            g_aux[l*CIN + o] = s*xk + c*xl;
        }
    }
}

// gemm (inline special-node path, bias add) + last-block outrot
__global__ void k_gemm(const float* h, const float* rw, const float* iw,
                       const float* cc, const float* bias, float* out) {
    __shared__ float sa[4][CIN];
    int tid = threadIdx.x;
    int r = tid >> 6, o = tid & 63;
    int n = blockIdx.x*4 + r;
    sa[r][o] = g_aux[n*CIN + o];
    __syncthreads();
    float wv = g_L[(size_t)n*N + n];
    float acc = 0.0f;
    if (wv == 1.0f) {
#pragma unroll 16
        for (int i = 0; i < CIN; i++)
            acc = fmaf(g_G1[i*COUT + o], sa[r][i], acc);
    } else {
        for (int i = 0; i < CIN; i++) {
            int oi = o*CIN + i;
            acc = fmaf(g_entry(wv, h[oi], rw + oi*RWR, iw + oi*RWR, cc[oi]), sa[r][i], acc);
        }
    }
    out[n*COUT + o] = acc + bias[o];

    __shared__ bool isLast;
    if (tid == 0) {
        __threadfence();
        isLast = (atomicAdd(&g_arrG, 1u) == gridDim.x - 1u);
    }
    __syncthreads();
    if (!isLast) return;
    if (tid == 0) g_arrG = 0u;
    __threadfence();
    __syncthreads();
    if (tid < COUT) {
        int oo = tid;
        float b = bias[oo];
        for (int t = ITERS - 1; t >= 0; t--) {
            int k = g_rotk[t], l = g_rotl[t];
            float c = g_rotc[t], s = g_rots[t];
            float vk = __ldcg(&out[k*COUT + oo]) - b;
            float vl = __ldcg(&out[l*COUT + oo]) - b;
            out[k*COUT + oo] =  c*vk + s*vl + b;
            out[l*COUT + oo] = -s*vk + c*vl + b;
        }
    }
}

// ---------------- launch ----------------
extern "C" void kernel_launch(void* const* d_in, const int* in_sizes, int n_in,
                              void* d_out, int out_size) {
    const float* x    = (const float*)d_in[0];
    const int*   e    = (const int*)  d_in[1];
    const float* rw   = (const float*)d_in[2];
    const float* iw   = (const float*)d_in[3];
    const float* h    = (const float*)d_in[4];
    const float* cc   = (const float*)d_in[5];
    const float* bias = (const float*)d_in[6];
    float* out = (float*)d_out;
    int E = in_sizes[1] / 2;   // edge_index shape (2, E)

    k_setup<<<16, 256>>>(e);
    k_bucket<<<512, 256>>>(e, E);
    k_dinv<<<16, 256>>>();
    k_transform_rowmax<<<N, 256>>>();
    k_jacobi<<<JB, JT>>>(h, rw, iw, cc, x);
    k_gemm<<<N/4, 256>>>(h, rw, iw, cc, bias, out);
}

// round 11
// speedup vs baseline: 1.5411x; 1.5411x over previous
#include <cuda_runtime.h>

typedef unsigned long long u64;
typedef unsigned int u32;

#define N 4096
#define NN (N*N)
#define CIN 64
#define COUT 64
#define RWR 4
#define ITERS 10
#define BW 256
#define NSEG 32
#define SEGW 128
// packed (val=0, col=0xFFFFF) — never wins (global max > 0), col decode stays small
#define EMPTYP 0x00000000FFF00000ULL

// ---------------- device scratch (static globals: no allocations) ----------------
__device__ __align__(16) float g_L[NN];       // 64MB Jacobi working matrix
__device__ int   g_cursor[N];                 // per-row fill cursor == degree
__device__ int   g_bucket[N*BW];              // fixed-width adjacency
__device__ __align__(16) float g_dinv[N];
__device__ __align__(16) float g_aux[N*CIN];
__device__ float g_G1[CIN*COUT];              // [i][o]
__device__ int   g_is64;
__device__ int   g_rotk[ITERS], g_rotl[ITERS];
__device__ float g_rotc[ITERS], g_rots[ITERS];
__device__ u64   g_seg[N*NSEG];               // per-row per-128-col lexmax, strict upper
__device__ u64   g_rowpack[N];                // per-row lexmax (packed)
__device__ u64   g_pivseg[2*NSEG];            // pivot-row rebuild accumulators
__device__ unsigned g_arrT, g_arrR, g_arrA, g_arrG;

// pack (val >= 0, col) so that u64 integer max == lexmax(val desc, col asc)
__device__ __forceinline__ u64 packvc(float v, int col) {
    return ((u64)__float_as_uint(v) << 32) | (u32)(0xFFFFFFFFu - (u32)col);
}
__device__ __forceinline__ float unpv(u64 p) { return __uint_as_float((u32)(p >> 32)); }
__device__ __forceinline__ int   unpc(u64 p) { return (int)(0xFFFFFFFFu - (u32)p); }

__device__ __forceinline__ int edge_at(const int* e, int j) {
    return g_is64 ? e[2*j] : e[j];      // int64: value in low word
}

// ---- global argmax over packed row maxima + rotation params (reference RN path) ----
// Runs in ONE block (256 threads). Rowpacks/g_L read via __ldcg (L2 coherence point).
__device__ void argmax_params(int it, int tid) {
    __shared__ float sv[256];
    __shared__ int   si[256];
    float bval = -1.0f; int bflat = 0x7FFFFFFF;
    for (int i = tid; i < N; i += 256) {
        u64 p = __ldcg(&g_rowpack[i]);
        float v = unpv(p);
        int flat = i*N + unpc(p);
        if (v > bval || (v == bval && flat < bflat)) { bval = v; bflat = flat; }
    }
    sv[tid] = bval; si[tid] = bflat;
    __syncthreads();
    for (int off = 128; off > 0; off >>= 1) {
        if (tid < off) {
            float v = sv[tid+off]; int f = si[tid+off];
            if (v > sv[tid] || (v == sv[tid] && f < si[tid])) { sv[tid] = v; si[tid] = f; }
        }
        __syncthreads();
    }
    if (tid == 0) {
        int idx = si[0];
        int k = idx >> 12, l = idx & (N-1);
        float akl = __ldcg(&g_L[(size_t)k*N + l]);
        float akk = __ldcg(&g_L[(size_t)k*N + k]);
        float all = __ldcg(&g_L[(size_t)l*N + l]);
        float aDiff = __fsub_rn(all, akk);
        float akl_safe   = (akl   == 0.0f) ? 1.0f : akl;
        float aDiff_safe = (aDiff == 0.0f) ? 1.0f : aDiff;
        float phi = __fdiv_rn(aDiff, __fmul_rn(2.0f, akl_safe));
        float t2 = __fdiv_rn(1.0f, __fadd_rn(fabsf(phi),
                     __fsqrt_rn(__fadd_rn(__fmul_rn(phi, phi), 1.0f))));
        if (phi < 0.0f) t2 = -t2;
        float t1 = __fdiv_rn(akl, aDiff_safe);
        float tt = (fabsf(akl) < __fmul_rn(fabsf(aDiff), 1e-36f)) ? t1 : t2;
        float cv = __fdiv_rn(1.0f, __fsqrt_rn(__fadd_rn(__fmul_rn(tt, tt), 1.0f)));
        float ss = __fmul_rn(tt, cv);
        g_rotk[it] = k; g_rotl[it] = l; g_rotc[it] = cv; g_rots[it] = ss;
    }
}

// ---------------- setup ----------------
__global__ void k_setup(const int* e) {
    int t = blockIdx.x*blockDim.x + threadIdx.x;
    if (t < N) g_cursor[t] = 0;
    if (t < 2*NSEG) g_pivseg[t] = 0ULL;
    if (t == 0) {
        int nz = 0;
        for (int j = 1; j < 512; j += 2) nz |= (e[j] != 0);
        g_is64 = nz ? 0 : 1;
        g_arrT = 0u; g_arrR = 0u; g_arrA = 0u; g_arrG = 0u;
    }
}

__global__ void k_bucket(const int* e, int E) {
    for (int j = blockIdx.x*blockDim.x + threadIdx.x; j < E; j += gridDim.x*blockDim.x) {
        int r = edge_at(e, j);
        int c = edge_at(e, E + j);
        int p = atomicAdd(&g_cursor[r], 1);
        if (p < BW) g_bucket[r*BW + p] = c;
    }
}

__global__ void k_dinv() {
    int t = blockIdx.x*blockDim.x + threadIdx.x;
    if (t < N) {
        float d = (float)g_cursor[t];
        g_dinv[t] = (d > 0.0f) ? __fdiv_rn(1.0f, __fsqrt_rn(d)) : 0.0f;
    }
}

// Write L from scratch; build per-segment packed lexmax + rowpack.
// Last arriving block: argmax + rotation params for iteration 0.
__global__ void k_transform() {
    __shared__ __align__(16) float cnt[N];   // 16KB
    __shared__ u64 spack[NSEG];
    int i = blockIdx.x, tid = threadIdx.x;
    int lane = tid & 31, w = tid >> 5;
    for (int j = tid; j < N; j += 256) cnt[j] = 0.0f;
    __syncthreads();
    int deg = g_cursor[i];
    for (int p = tid; p < deg; p += 256) atomicAdd(&cnt[g_bucket[i*BW + p]], 1.0f);
    __syncthreads();
    float di = g_dinv[i];
    float4* row = (float4*)(g_L + (size_t)i*N);
    const float4* dv4 = (const float4*)g_dinv;
    // warp w handles segments w, w+8, w+16, w+24 (32 float4 lanes per segment)
    for (int s = w; s < NSEG; s += 8) {
        int t4 = s*32 + lane;
        int j = t4*4;
        float4 dj = dv4[t4];
        float4 cv = *((float4*)&cnt[j]);
        float4 o;
        o.x = __fsub_rn((i==j  )?1.0f:0.0f, __fmul_rn(__fmul_rn(di, cv.x), dj.x));
        o.y = __fsub_rn((i==j+1)?1.0f:0.0f, __fmul_rn(__fmul_rn(di, cv.y), dj.y));
        o.z = __fsub_rn((i==j+2)?1.0f:0.0f, __fmul_rn(__fmul_rn(di, cv.z), dj.z));
        o.w = __fsub_rn((i==j+3)?1.0f:0.0f, __fmul_rn(__fmul_rn(di, cv.w), dj.w));
        row[t4] = o;
        u64 best = EMPTYP;
        if (j+0 > i) { u64 q = packvc(fabsf(o.x), j+0); if (q > best) best = q; }
        if (j+1 > i) { u64 q = packvc(fabsf(o.y), j+1); if (q > best) best = q; }
        if (j+2 > i) { u64 q = packvc(fabsf(o.z), j+2); if (q > best) best = q; }
        if (j+3 > i) { u64 q = packvc(fabsf(o.w), j+3); if (q > best) best = q; }
#pragma unroll
        for (int off = 16; off > 0; off >>= 1) {
            u64 q = __shfl_down_sync(0xFFFFFFFFu, best, off);
            if (q > best) best = q;
        }
        if (lane == 0) { g_seg[i*NSEG + s] = best; spack[s] = best; }
    }
    __syncthreads();
    if (tid < 32) {
        u64 p = spack[tid];
#pragma unroll
        for (int off = 16; off > 0; off >>= 1) {
            u64 q = __shfl_down_sync(0xFFFFFFFFu, p, off);
            if (q > p) p = q;
        }
        if (tid == 0) g_rowpack[i] = p;
    }
    // last arriving block: iteration-0 argmax + params
    __shared__ bool isLast;
    __syncthreads();
    if (tid == 0) {
        __threadfence();
        isLast = (atomicAdd(&g_arrT, 1u) == gridDim.x - 1u);
    }
    __syncthreads();
    if (!isLast) return;
    if (tid == 0) g_arrT = 0u;
    __threadfence();
    __syncthreads();
    argmax_params(0, tid);
}

// own-row segment maintenance after (i,col) changed to |val| (thread-local, exact)
__device__ __forceinline__ void seg_handle(int i, int col, float val) {
    int s = col >> 7;
    u64 p = g_seg[i*NSEG + s];
    if (unpc(p) == col) {
        // old segment argmax invalidated: rescan 128 entries (all thread-local-fresh)
        int j0 = s << 7; if (j0 <= i) j0 = i + 1;
        int j1 = (s << 7) + SEGW;
        u64 best = EMPTYP;
        const float* rowp = g_L + (size_t)i*N;
#pragma unroll 4
        for (int j = j0; j < j1; j++) {
            u64 q = packvc(fabsf(rowp[j]), j);
            if (q > best) best = q;
        }
        g_seg[i*NSEG + s] = best;
    } else {
        u64 q = packvc(val, col);
        if (q > p) g_seg[i*NSEG + s] = q;
    }
}

// One launch per Jacobi iteration: rotation + all max bookkeeping + next argmax.
__global__ void __launch_bounds__(256) k_rotate2(int it) {   // grid 16 x 256 == N threads
    __shared__ u64 sp[2*NSEG];
    int tid = threadIdx.x;
    int i = blockIdx.x*256 + tid;
    if (tid < 2*NSEG) sp[tid] = 0ULL;
    __syncthreads();
    int k = g_rotk[it], l = g_rotl[it];
    float c = g_rotc[it], s = g_rots[it];

    if (i == k) {
        // 2x2 pivot block: column pass then row pass (bitwise reference order)
        float akk = g_L[(size_t)k*N + k], akl = g_L[(size_t)k*N + l];
        float alk = g_L[(size_t)l*N + k], all = g_L[(size_t)l*N + l];
        float akk1 = __fsub_rn(__fmul_rn(c, akk), __fmul_rn(s, akl));
        float akl1 = __fadd_rn(__fmul_rn(s, akk), __fmul_rn(c, akl));
        float alk1 = __fsub_rn(__fmul_rn(c, alk), __fmul_rn(s, all));
        float all1 = __fadd_rn(__fmul_rn(s, alk), __fmul_rn(c, all));
        float akk2 = __fsub_rn(__fmul_rn(c, akk1), __fmul_rn(s, alk1));
        float all2 = __fadd_rn(__fmul_rn(s, akl1), __fmul_rn(c, all1));
        g_L[(size_t)k*N + k] = akk2;
        g_L[(size_t)l*N + l] = all2;
        g_L[(size_t)k*N + l] = 0.0f;   // val 0 never wins a segment max
        g_L[(size_t)l*N + k] = 0.0f;
    } else if (i != l) {
        // column update of own row
        float ck = g_L[(size_t)i*N + k], cl = g_L[(size_t)i*N + l];
        float nk = __fsub_rn(__fmul_rn(c, ck), __fmul_rn(s, cl));
        float nl = __fadd_rn(__fmul_rn(s, ck), __fmul_rn(c, cl));
        g_L[(size_t)i*N + k] = nk;
        g_L[(size_t)i*N + l] = nl;
        // row-pass update of pivot rows at own column
        float rk = g_L[(size_t)k*N + i], rl = g_L[(size_t)l*N + i];
        float nrk = __fsub_rn(__fmul_rn(c, rk), __fmul_rn(s, rl));
        float nrl = __fadd_rn(__fmul_rn(s, rk), __fmul_rn(c, rl));
        g_L[(size_t)k*N + i] = nrk;
        g_L[(size_t)l*N + i] = nrl;
        // contribute pivot-row upper entries to rebuild accumulators
        if (i > k) atomicMax(&sp[i >> 7],        packvc(fabsf(nrk), i));
        if (i > l) atomicMax(&sp[NSEG + (i>>7)], packvc(fabsf(nrl), i));
        // own-row segment maintenance + rowpack
        if (k > i || l > i) {
            if (k > i) seg_handle(i, k, fabsf(nk));
            if (l > i) seg_handle(i, l, fabsf(nl));
            u64 best = 0ULL;
            int s0 = i >> 7;
            for (int sg = s0; sg < NSEG; sg++) {
                u64 p = g_seg[i*NSEG + sg];
                if (p > best) best = p;
            }
            g_rowpack[i] = best;
        }
    }
    __syncthreads();
    if (tid < 2*NSEG) {
        u64 v = sp[tid];
        if (v) atomicMax(&g_pivseg[tid], v);
    }
    // last arriving block: finalize pivot rows, argmax + params for it+1
    __shared__ bool isLast;
    __syncthreads();
    if (tid == 0) {
        __threadfence();
        isLast = (atomicAdd(&g_arrR, 1u) == gridDim.x - 1u);
    }
    __syncthreads();
    if (!isLast || it + 1 >= ITERS) return;
    if (tid == 0) g_arrR = 0u;
    __threadfence();
    __syncthreads();
    if (tid < 2*NSEG) {
        int r = (tid < NSEG) ? k : l;
        g_seg[r*NSEG + (tid & (NSEG-1))] = __ldcg(&g_pivseg[tid]);
    }
    if (tid < 2) {
        int r = (tid == 0) ? k : l;
        u64 best = 0ULL;
        for (int sg = 0; sg < NSEG; sg++) {
            u64 p = __ldcg(&g_pivseg[tid*NSEG + sg]);
            if (p > best) best = p;
        }
        g_rowpack[r] = best;
    }
    __syncthreads();
    if (tid < 2*NSEG) g_pivseg[tid] = 0ULL;      // reset for next iteration
    if (tid == 0) __threadfence();
    __syncthreads();
    argmax_params(it + 1, tid);
}

// ---------------- Cayley filter helper ----------------
__device__ __forceinline__ float g_entry(float wv, float hoi,
                                         const float* rw, const float* iw, float cval) {
    float hw = __fmul_rn(hoi, wv);
    float a2 = (hw > 1e-5f) ? 2.0f * atanf(__fdiv_rn(1.0f, hw)) : 2.0f;
    float acc = cval;
#pragma unroll
    for (int r = 0; r < RWR; r++) {
        float th = a2 * (float)(r + 1);
        float sn, cs;
        sincosf(th, &sn, &cs);
        acc += rw[r]*cs - iw[r]*sn;
    }
    return acc;
}

// tail: aux = x copy (all blocks) + G1 (block 0) + auxrot (last arriving block)
__global__ void k_tail(const float* h, const float* rw, const float* iw,
                       const float* cc, const float* x) {
    int tid = threadIdx.x, bid = blockIdx.x;
    int gt = bid*256 + tid;
    const float4* xi = (const float4*)x;
    float4* ao = (float4*)g_aux;
    for (int idx = gt; idx < N*CIN/4; idx += gridDim.x*256) ao[idx] = xi[idx];
    if (bid == 0) {
        for (int t = tid; t < COUT*CIN; t += 256) {
            int o = t >> 6, i2 = t & 63;
            int oi = o*CIN + i2;
            g_G1[i2*COUT + o] = g_entry(1.0f, h[oi], rw + oi*RWR, iw + oi*RWR, cc[oi]);
        }
    }
    __shared__ bool isLast;
    __syncthreads();
    if (tid == 0) {
        __threadfence();
        isLast = (atomicAdd(&g_arrA, 1u) == gridDim.x - 1u);
    }
    __syncthreads();
    if (!isLast) return;
    if (tid == 0) g_arrA = 0u;
    __threadfence();
    __syncthreads();
    if (tid < CIN) {   // aux = U^T x (apply R1^T first); columns independent
        int o = tid;
        for (int t = 0; t < ITERS; t++) {
            int k = g_rotk[t], l = g_rotl[t];
            float c = g_rotc[t], s = g_rots[t];
            float xk = __ldcg(&g_aux[k*CIN + o]), xl = __ldcg(&g_aux[l*CIN + o]);
            g_aux[k*CIN + o] = c*xk - s*xl;
            g_aux[l*CIN + o] = s*xk + c*xl;
        }
    }
}

// gemm (inline special-node path, bias add) + last-block outrot
__global__ void k_gemm(const float* h, const float* rw, const float* iw,
                       const float* cc, const float* bias, float* out) {
    __shared__ float sa[4][CIN];
    int tid = threadIdx.x;
    int r = tid >> 6, o = tid & 63;
    int n = blockIdx.x*4 + r;
    sa[r][o] = g_aux[n*CIN + o];
    __syncthreads();
    float wv = g_L[(size_t)n*N + n];
    float acc = 0.0f;
    if (wv == 1.0f) {
#pragma unroll 16
        for (int i = 0; i < CIN; i++)
            acc = fmaf(g_G1[i*COUT + o], sa[r][i], acc);
    } else {
        for (int i = 0; i < CIN; i++) {
            int oi = o*CIN + i;
            acc = fmaf(g_entry(wv, h[oi], rw + oi*RWR, iw + oi*RWR, cc[oi]), sa[r][i], acc);
        }
    }
    out[n*COUT + o] = acc + bias[o];

    __shared__ bool isLast;
    if (tid == 0) {
        __threadfence();
        isLast = (atomicAdd(&g_arrG, 1u) == gridDim.x - 1u);
    }
    __syncthreads();
    if (!isLast) return;
    if (tid == 0) g_arrG = 0u;
    __threadfence();
    __syncthreads();
    if (tid < COUT) {  // out = U * outT (apply R10 first); bias compensation exact (bias==0)
        int oo = tid;
        float b = bias[oo];
        for (int t = ITERS - 1; t >= 0; t--) {
            int k = g_rotk[t], l = g_rotl[t];
            float c = g_rotc[t], s = g_rots[t];
            float vk = __ldcg(&out[k*COUT + oo]) - b;
            float vl = __ldcg(&out[l*COUT + oo]) - b;
            out[k*COUT + oo] =  c*vk + s*vl + b;
            out[l*COUT + oo] = -s*vk + c*vl + b;
        }
    }
}

// ---------------- launch ----------------
extern "C" void kernel_launch(void* const* d_in, const int* in_sizes, int n_in,
                              void* d_out, int out_size) {
    const float* x    = (const float*)d_in[0];
    const int*   e    = (const int*)  d_in[1];
    const float* rw   = (const float*)d_in[2];
    const float* iw   = (const float*)d_in[3];
    const float* h    = (const float*)d_in[4];
    const float* cc   = (const float*)d_in[5];
    const float* bias = (const float*)d_in[6];
    float* out = (float*)d_out;
    int E = in_sizes[1] / 2;   // edge_index shape (2, E)

    k_setup<<<16, 256>>>(e);
    k_bucket<<<512, 256>>>(e, E);
    k_dinv<<<16, 256>>>();
    k_transform<<<N, 256>>>();
    for (int it = 0; it < ITERS; it++)
        k_rotate2<<<N/256, 256>>>(it);
    k_tail<<<64, 256>>>(h, rw, iw, cc, x);
    k_gemm<<<N/4, 256>>>(h, rw, iw, cc, bias, out);
}

// round 12
// speedup vs baseline: 1.7446x; 1.1320x over previous
#include <cuda_runtime.h>

#define N 4096
#define NN (N*N)
#define CIN 64
#define COUT 64
#define RWR 4
#define ITERS 10
#define BW 256          // bucket width (max supported row degree)
#define RB 64           // rescan blocks

// ---------------- device scratch (static globals: no allocations) ----------------
__device__ __align__(16) float g_L[NN];       // 64MB Jacobi working matrix
__device__ int   g_cursor[N];                 // per-row fill cursor == degree
__device__ int   g_bucket[N*BW];              // fixed-width adjacency
__device__ __align__(16) float g_dinv[N];
__device__ __align__(16) float g_aux[N*CIN];
__device__ float g_G1[CIN*COUT];              // [i][o]
__device__ int   g_is64;
__device__ int   g_rotk[ITERS], g_rotl[ITERS];
__device__ float g_rotc[ITERS], g_rots[ITERS];
__device__ float g_rowval[N];
__device__ int   g_rowidx[N];
__device__ int   g_rlist[N];
__device__ int   g_rn;
__device__ unsigned g_arrB, g_arrT, g_arrR, g_arrA, g_arrG;

__device__ __forceinline__ int edge_at(const int* e, int j) {
    return g_is64 ? e[2*j] : e[j];      // int64: value in low word
}

__device__ __forceinline__ void block_lexmax(float* sv, int* si, int tid, int nthr) {
    for (int off = nthr/2; off > 0; off >>= 1) {
        if (tid < off) {
            float v = sv[tid+off]; int c = si[tid+off];
            if (v > sv[tid] || (v == sv[tid] && c < si[tid])) { sv[tid] = v; si[tid] = c; }
        }
        __syncthreads();
    }
}

// argmax over g_rowval + rotation params for iteration `it` (reference RN arithmetic).
// Runs in ONE block; rowvals/L read via __ldcg (post-fence L2 coherence).
__device__ __forceinline__ void argmax_and_params(int it, float* sv, int* si, int tid, int nthr) {
    float best = -1.0f; int bflat = 0x7FFFFFFF;
    for (int i = tid; i < N; i += nthr) {
        float v = __ldcg(&g_rowval[i]);
        if (v >= 0.0f) {
            int flat = i*N + __ldcg(&g_rowidx[i]);
            if (v > best || (v == best && flat < bflat)) { best = v; bflat = flat; }
        }
    }
    sv[tid] = best; si[tid] = bflat;
    __syncthreads();
    block_lexmax(sv, si, tid, nthr);
    if (tid == 0) {
        int idx = si[0];
        int k = idx >> 12, l = idx & (N-1);
        float akl = __ldcg(&g_L[(size_t)k*N + l]);
        float akk = __ldcg(&g_L[(size_t)k*N + k]);
        float all = __ldcg(&g_L[(size_t)l*N + l]);
        float aDiff = __fsub_rn(all, akk);
        float akl_safe   = (akl   == 0.0f) ? 1.0f : akl;
        float aDiff_safe = (aDiff == 0.0f) ? 1.0f : aDiff;
        float phi = __fdiv_rn(aDiff, __fmul_rn(2.0f, akl_safe));
        float t2 = __fdiv_rn(1.0f, __fadd_rn(fabsf(phi),
                     __fsqrt_rn(__fadd_rn(__fmul_rn(phi, phi), 1.0f))));
        if (phi < 0.0f) t2 = -t2;
        float t1 = __fdiv_rn(akl, aDiff_safe);
        float tt = (fabsf(akl) < __fmul_rn(fabsf(aDiff), 1e-36f)) ? t1 : t2;
        float cv = __fdiv_rn(1.0f, __fsqrt_rn(__fadd_rn(__fmul_rn(tt, tt), 1.0f)));
        float ss = __fmul_rn(tt, cv);
        g_rotk[it] = k; g_rotl[it] = l; g_rotc[it] = cv; g_rots[it] = ss;
        g_rn = 0;
    }
}

// ---------------- setup ----------------
__global__ void k_setup(const int* e) {
    int t = blockIdx.x*blockDim.x + threadIdx.x;
    if (t < N) g_cursor[t] = 0;
    if (t == 0) {
        int nz = 0;
        for (int j = 1; j < 512; j += 2) nz |= (e[j] != 0);
        g_is64 = nz ? 0 : 1;
        g_rn = 0;
        g_arrB = 0u; g_arrT = 0u; g_arrR = 0u; g_arrA = 0u; g_arrG = 0u;
    }
}

// scatter edges into fixed-width buckets; last arriving block computes dinv
__global__ void k_bucket(const int* e, int E) {
    for (int j = blockIdx.x*blockDim.x + threadIdx.x; j < E; j += gridDim.x*blockDim.x) {
        int r = edge_at(e, j);
        int c = edge_at(e, E + j);
        int p = atomicAdd(&g_cursor[r], 1);
        if (p < BW) g_bucket[r*BW + p] = c;
    }
    __shared__ bool isLast;
    int tid = threadIdx.x;
    if (tid == 0) {
        __threadfence();
        isLast = (atomicAdd(&g_arrB, 1u) == gridDim.x - 1u);
    }
    __syncthreads();
    if (!isLast) return;
    if (tid == 0) g_arrB = 0u;
    for (int t = tid; t < N; t += blockDim.x) {
        float d = (float)__ldcg(&g_cursor[t]);
        g_dinv[t] = (d > 0.0f) ? __fdiv_rn(1.0f, __fsqrt_rn(d)) : 0.0f;
    }
}

// Write L from scratch; per-row max via cheap fmaxf pass + first-index pass.
// Last arriving block: argmax + rotation params for iteration 0.
__global__ void k_transform_rowmax() {
    __shared__ __align__(16) float cnt[N];   // 16KB
    __shared__ float sv[256];
    __shared__ int   si[256];
    int i = blockIdx.x, tid = threadIdx.x;
    for (int j = tid; j < N; j += 256) cnt[j] = 0.0f;
    __syncthreads();
    int deg = g_cursor[i];
    for (int p = tid; p < deg; p += 256) atomicAdd(&cnt[g_bucket[i*BW + p]], 1.0f);
    __syncthreads();
    float di = g_dinv[i];
    float4* row = (float4*)(g_L + (size_t)i*N);
    const float4* dv4 = (const float4*)g_dinv;
    // pass 1: write row, track plain value max over strict-upper entries
    float vmax = -1.0f;
    for (int t4 = tid; t4 < N/4; t4 += 256) {
        int j = t4*4;
        float4 dj = dv4[t4];
        float4 cv = *((float4*)&cnt[j]);
        float4 o;
        o.x = __fsub_rn((i==j  )?1.0f:0.0f, __fmul_rn(__fmul_rn(di, cv.x), dj.x));
        o.y = __fsub_rn((i==j+1)?1.0f:0.0f, __fmul_rn(__fmul_rn(di, cv.y), dj.y));
        o.z = __fsub_rn((i==j+2)?1.0f:0.0f, __fmul_rn(__fmul_rn(di, cv.z), dj.z));
        o.w = __fsub_rn((i==j+3)?1.0f:0.0f, __fmul_rn(__fmul_rn(di, cv.w), dj.w));
        row[t4] = o;
        float a0 = (j+0 > i) ? fabsf(o.x) : -1.0f;
        float a1 = (j+1 > i) ? fabsf(o.y) : -1.0f;
        float a2 = (j+2 > i) ? fabsf(o.z) : -1.0f;
        float a3 = (j+3 > i) ? fabsf(o.w) : -1.0f;
        vmax = fmaxf(vmax, fmaxf(fmaxf(a0, a1), fmaxf(a2, a3)));
    }
    sv[tid] = vmax;
    __syncthreads();
    for (int off = 128; off > 0; off >>= 1) {
        if (tid < off) sv[tid] = fmaxf(sv[tid], sv[tid+off]);
        __syncthreads();
    }
    float bmax = sv[0];
    // pass 2: only threads whose local max hit bmax search for the first column
    int bidx = 0x7FFFFFFF;
    if (bmax >= 0.0f && vmax == bmax) {
        for (int t4 = tid; t4 < N/4; t4 += 256) {
            int j = t4*4;
            float4 o = row[t4];
            if (j+3 > i) {
                if (j+0 > i && fabsf(o.x) == bmax && j+0 < bidx) bidx = j+0;
                if (j+1 > i && fabsf(o.y) == bmax && j+1 < bidx) bidx = j+1;
                if (j+2 > i && fabsf(o.z) == bmax && j+2 < bidx) bidx = j+2;
                if (           fabsf(o.w) == bmax && j+3 < bidx) bidx = j+3;
            }
        }
    }
    si[tid] = bidx;
    __syncthreads();
    for (int off = 128; off > 0; off >>= 1) {
        if (tid < off) si[tid] = min(si[tid], si[tid+off]);
        __syncthreads();
    }
    if (tid == 0) { g_rowval[i] = bmax; g_rowidx[i] = si[0]; }

    // last arriving block: iteration-0 argmax + params
    __shared__ bool isLast;
    __syncthreads();
    if (tid == 0) {
        __threadfence();
        isLast = (atomicAdd(&g_arrT, 1u) == gridDim.x - 1u);
    }
    __syncthreads();
    if (!isLast) return;
    if (tid == 0) g_arrT = 0u;
    __threadfence();
    __syncthreads();
    argmax_and_params(0, sv, si, tid, 256);
}

// Two-sided rotation + incremental rowmax maintenance (bitwise-exact vs reference).
__global__ void k_rotate(int it) {
    int i = blockIdx.x*blockDim.x + threadIdx.x;
    if (i >= N) return;
    int k = g_rotk[it], l = g_rotl[it];
    float c = g_rotc[it], s = g_rots[it];
    if (i != k && i != l) {
        float ck = g_L[(size_t)i*N + k], cl = g_L[(size_t)i*N + l];
        float nk = __fsub_rn(__fmul_rn(c, ck), __fmul_rn(s, cl));
        float nl = __fadd_rn(__fmul_rn(s, ck), __fmul_rn(c, cl));
        g_L[(size_t)i*N + k] = nk;
        g_L[(size_t)i*N + l] = nl;
        float rk = g_L[(size_t)k*N + i], rl = g_L[(size_t)l*N + i];
        g_L[(size_t)k*N + i] = __fsub_rn(__fmul_rn(c, rk), __fmul_rn(s, rl));
        g_L[(size_t)l*N + i] = __fadd_rn(__fmul_rn(s, rk), __fmul_rn(c, rl));
        float bv = g_rowval[i]; int bj = g_rowidx[i];
        if (bv >= 0.0f && (bj == k || bj == l)) {
            int p = atomicAdd(&g_rn, 1);
            g_rlist[p] = i;
        } else {
            bool ch = false;
            if (k > i) { float a = fabsf(nk); if (a > bv || (a == bv && k < bj)) { bv = a; bj = k; ch = true; } }
            if (l > i) { float a = fabsf(nl); if (a > bv || (a == bv && l < bj)) { bv = a; bj = l; ch = true; } }
            if (ch) { g_rowval[i] = bv; g_rowidx[i] = bj; }
        }
    } else if (i == k) {
        float akk = g_L[(size_t)k*N + k], akl = g_L[(size_t)k*N + l];
        float alk = g_L[(size_t)l*N + k], all = g_L[(size_t)l*N + l];
        float akk1 = __fsub_rn(__fmul_rn(c, akk), __fmul_rn(s, akl));
        float akl1 = __fadd_rn(__fmul_rn(s, akk), __fmul_rn(c, akl));
        float alk1 = __fsub_rn(__fmul_rn(c, alk), __fmul_rn(s, all));
        float all1 = __fadd_rn(__fmul_rn(s, alk), __fmul_rn(c, all));
        float akk2 = __fsub_rn(__fmul_rn(c, akk1), __fmul_rn(s, alk1));
        float all2 = __fadd_rn(__fmul_rn(s, akl1), __fmul_rn(c, all1));
        g_L[(size_t)k*N + k] = akk2;
        g_L[(size_t)l*N + l] = all2;
        g_L[(size_t)k*N + l] = 0.0f;
        g_L[(size_t)l*N + k] = 0.0f;
        int p = atomicAdd(&g_rn, 2);
        g_rlist[p] = k; g_rlist[p+1] = l;
    }
}

// Rescan flagged rows; last arriving block runs argmax + params for iteration `it`.
__global__ void k_rescan_argmax(int it) {
    __shared__ float sv[256];
    __shared__ int   si[256];
    int tid = threadIdx.x;
    int nr = g_rn;
    for (int b = blockIdx.x; b < nr; b += gridDim.x) {
        int i = g_rlist[b];
        const float* rowp = g_L + (size_t)i*N;
        float best = -1.0f; int bcol = 0x7FFFFFFF;
        for (int j = i + 1 + tid; j < N; j += 256) {
            float a = fabsf(__ldcg(&rowp[j]));
            if (a > best || (a == best && j < bcol)) { best = a; bcol = j; }
        }
        sv[tid] = best; si[tid] = bcol;
        __syncthreads();
        block_lexmax(sv, si, tid, 256);
        if (tid == 0) { g_rowval[i] = sv[0]; g_rowidx[i] = si[0]; }
        __syncthreads();
    }
    __shared__ bool isLast;
    if (tid == 0) {
        __threadfence();
        isLast = (atomicAdd(&g_arrR, 1u) == gridDim.x - 1u);
    }
    __syncthreads();
    if (!isLast) return;
    if (tid == 0) g_arrR = 0u;
    __threadfence();
    __syncthreads();
    argmax_and_params(it, sv, si, tid, 256);
}

// ---------------- Cayley filter helper ----------------
__device__ __forceinline__ float g_entry(float wv, float hoi,
                                         const float* rw, const float* iw, float cval) {
    float hw = __fmul_rn(hoi, wv);
    float a2 = (hw > 1e-5f) ? 2.0f * atanf(__fdiv_rn(1.0f, hw)) : 2.0f;
    float acc = cval;
#pragma unroll
    for (int r = 0; r < RWR; r++) {
        float th = a2 * (float)(r + 1);
        float sn, cs;
        sincosf(th, &sn, &cs);
        acc += rw[r]*cs - iw[r]*sn;
    }
    return acc;
}

// tail: aux = x copy (all blocks) + G1 (block 0) + auxrot (last arriving block)
__global__ void k_tail(const float* h, const float* rw, const float* iw,
                       const float* cc, const float* x) {
    int tid = threadIdx.x, bid = blockIdx.x;
    int gt = bid*256 + tid;
    const float4* xi = (const float4*)x;
    float4* ao = (float4*)g_aux;
    for (int idx = gt; idx < N*CIN/4; idx += gridDim.x*256) ao[idx] = xi[idx];
    if (bid == 0) {
        for (int t = tid; t < COUT*CIN; t += 256) {
            int o = t >> 6, i2 = t & 63;
            int oi = o*CIN + i2;
            g_G1[i2*COUT + o] = g_entry(1.0f, h[oi], rw + oi*RWR, iw + oi*RWR, cc[oi]);
        }
    }
    __shared__ bool isLast;
    __syncthreads();
    if (tid == 0) {
        __threadfence();
        isLast = (atomicAdd(&g_arrA, 1u) == gridDim.x - 1u);
    }
    __syncthreads();
    if (!isLast) return;
    if (tid == 0) g_arrA = 0u;
    __threadfence();
    __syncthreads();
    if (tid < CIN) {   // aux = U^T x (apply R1^T first); columns independent
        int o = tid;
        for (int t = 0; t < ITERS; t++) {
            int k = g_rotk[t], l = g_rotl[t];
            float c = g_rotc[t], s = g_rots[t];
            float xk = __ldcg(&g_aux[k*CIN + o]), xl = __ldcg(&g_aux[l*CIN + o]);
            g_aux[k*CIN + o] = c*xk - s*xl;
            g_aux[l*CIN + o] = s*xk + c*xl;
        }
    }
}

// gemm (inline special-node path, bias add) + last-block outrot
__global__ void k_gemm(const float* h, const float* rw, const float* iw,
                       const float* cc, const float* bias, float* out) {
    __shared__ float sa[4][CIN];
    int tid = threadIdx.x;
    int r = tid >> 6, o = tid & 63;
    int n = blockIdx.x*4 + r;
    sa[r][o] = g_aux[n*CIN + o];
    __syncthreads();
    float wv = g_L[(size_t)n*N + n];
    float acc = 0.0f;
    if (wv == 1.0f) {
#pragma unroll 16
        for (int i = 0; i < CIN; i++)
            acc = fmaf(g_G1[i*COUT + o], sa[r][i], acc);
    } else {
        for (int i = 0; i < CIN; i++) {
            int oi = o*CIN + i;
            acc = fmaf(g_entry(wv, h[oi], rw + oi*RWR, iw + oi*RWR, cc[oi]), sa[r][i], acc);
        }
    }
    out[n*COUT + o] = acc + bias[o];

    __shared__ bool isLast;
    if (tid == 0) {
        __threadfence();
        isLast = (atomicAdd(&g_arrG, 1u) == gridDim.x - 1u);
    }
    __syncthreads();
    if (!isLast) return;
    if (tid == 0) g_arrG = 0u;
    __threadfence();
    __syncthreads();
    if (tid < COUT) {  // out = U * outT (apply R10 first); bias compensation exact (bias==0)
        int oo = tid;
        float b = bias[oo];
        for (int t = ITERS - 1; t >= 0; t--) {
            int k = g_rotk[t], l = g_rotl[t];
            float c = g_rotc[t], s = g_rots[t];
            float vk = __ldcg(&out[k*COUT + oo]) - b;
            float vl = __ldcg(&out[l*COUT + oo]) - b;
            out[k*COUT + oo] =  c*vk + s*vl + b;
            out[l*COUT + oo] = -s*vk + c*vl + b;
        }
    }
}

// ---------------- launch ----------------
extern "C" void kernel_launch(void* const* d_in, const int* in_sizes, int n_in,
                              void* d_out, int out_size) {
    const float* x    = (const float*)d_in[0];
    const int*   e    = (const int*)  d_in[1];
    const float* rw   = (const float*)d_in[2];
    const float* iw   = (const float*)d_in[3];
    const float* h    = (const float*)d_in[4];
    const float* cc   = (const float*)d_in[5];
    const float* bias = (const float*)d_in[6];
    float* out = (float*)d_out;
    int E = in_sizes[1] / 2;   // edge_index shape (2, E)

    k_setup<<<16, 256>>>(e);
    k_bucket<<<512, 256>>>(e, E);
    k_transform_rowmax<<<N, 256>>>();
    for (int it = 0; it < ITERS; it++) {
        k_rotate<<<16, 256>>>(it);
        if (it + 1 < ITERS) k_rescan_argmax<<<RB, 256>>>(it + 1);
    }
    k_tail<<<64, 256>>>(h, rw, iw, cc, x);
    k_gemm<<<N/4, 256>>>(h, rw, iw, cc, bias, out);
}